// round 9
// baseline (speedup 1.0000x reference)
#include <cuda_runtime.h>
#include <math.h>

#define NN   50000
#define EE   800000
#define IN_C 128
#define HID  256
#define EMBD 128
#define RR   4
#define NBLK ((NN + 255) / 256)

// ---------------- scratch (device globals; no allocation) ----------------
__device__ int      g_deg[NN];
__device__ float    g_invdeg[NN];
__device__ int      g_cnt4[NN * RR];
__device__ float    g_invcnt4[NN * RR];
__device__ int      g_rowstart[NN];
__device__ int      g_cursor[NN];
__device__ int      g_bsum[256];
__device__ int      g_boff[256];
__device__ int      g_es[EE];
__device__ int      g_etl[EE];
__device__ float    g_xr[(size_t)NN * IN_C];
__device__ float    g_agg1[(size_t)NN * IN_C];
__device__ float    g_x1[(size_t)NN * HID];
__device__ float    g_agg2[(size_t)NN * HID];
__device__ float    g_xsage[(size_t)NN * HID];
__device__ float    g_h[(size_t)NN * 2 * HID];
__device__ float    g_als[NN * 2];
__device__ float    g_ald[NN * 2];
__device__ float    g_xgat[(size_t)NN * HID];
__device__ float    g_xt[(size_t)RR * NN * EMBD];
__device__ float    g_xrgcn[(size_t)NN * EMBD];
__device__ float    g_fb2[EMBD];
__device__ float    g_bt1r[256 * 128];
__device__ float    g_bt1l[256 * 128];
__device__ float    g_bt2[256 * 512];
__device__ float    g_btg[512 * 256];
__device__ float    g_btrel[RR * 128 * 256];
__device__ float    g_btfus[128 * 640];

__device__ __forceinline__ float lrelu(float v) { return v > 0.f ? v : 0.2f * v; }

__device__ __forceinline__ unsigned f2tf32(float f) {
    unsigned r;
    asm("cvt.rna.tf32.f32 %0, %1;" : "=r"(r) : "f"(f));
    return r;
}
__device__ __forceinline__ float rtf(float f) { return __uint_as_float(f2tf32(f)); }

#define CP16(sm, gm) asm volatile("cp.async.cg.shared.global [%0], [%1], 16;" :: "r"(sm), "l"(gm))
#define CPCOMMIT()   asm volatile("cp.async.commit_group;")
#define CPWAIT(n)    asm volatile("cp.async.wait_group %0;" :: "n"(n))

// ---------------- zero / counts / scan / fill ----------------
__global__ void k_zero_small() {
    int i = blockIdx.x * blockDim.x + threadIdx.x;
    if (i < NN) { g_deg[i] = 0; g_cursor[i] = 0; }
    if (i < NN * RR) g_cnt4[i] = 0;
}

__global__ void k_count(const int* __restrict__ dst, const int* __restrict__ et) {
    int i = blockIdx.x * blockDim.x + threadIdx.x;
    if (i >= EE) return;
    int d = dst[i];
    atomicAdd(&g_deg[d], 1);
    atomicAdd(&g_cnt4[d * RR + et[i]], 1);
}

__global__ void k_scan1() {
    __shared__ int sh[256];
    int b = blockIdx.x, t = threadIdx.x;
    int i = b * 256 + t;
    int v = (i < NN) ? g_deg[i] : 0;
    sh[t] = v; __syncthreads();
    for (int o = 1; o < 256; o <<= 1) {
        int add = (t >= o) ? sh[t - o] : 0;
        __syncthreads();
        sh[t] += add;
        __syncthreads();
    }
    if (i < NN) g_rowstart[i] = sh[t] - v;
    if (t == 255) g_bsum[b] = sh[255];
}

__global__ void k_scan2() {
    __shared__ int sh[256];
    int t = threadIdx.x;
    int v = (t < NBLK) ? g_bsum[t] : 0;
    sh[t] = v; __syncthreads();
    for (int o = 1; o < 256; o <<= 1) {
        int add = (t >= o) ? sh[t - o] : 0;
        __syncthreads();
        sh[t] += add;
        __syncthreads();
    }
    g_boff[t] = sh[t] - v;
}

__global__ void k_scan3_inv() {
    int i = blockIdx.x * blockDim.x + threadIdx.x;
    if (i >= NN) return;
    g_rowstart[i] += g_boff[i >> 8];
    g_invdeg[i] = 1.f / fmaxf((float)g_deg[i], 1.f);
#pragma unroll
    for (int r = 0; r < RR; r++)
        g_invcnt4[i * RR + r] = 1.f / fmaxf((float)g_cnt4[i * RR + r], 1.f);
}

__global__ void k_fill(const int* __restrict__ src, const int* __restrict__ dst,
                       const int* __restrict__ et) {
    int e = blockIdx.x * blockDim.x + threadIdx.x;
    if (e >= EE) return;
    int d = dst[e];
    int pos = atomicAdd(&g_cursor[d], 1);
    int slot = g_rowstart[d] + pos;
    g_es[slot] = src[e];
    g_etl[slot] = et[e];
}

// ---------------- weight transpose (+tf32 round) ----------------
__global__ void k_transB(const float* __restrict__ B, float* __restrict__ Bt,
                         int K, int N, int ldBt, int kOff) {
    int i = blockIdx.x * blockDim.x + threadIdx.x;
    if (i >= K * N) return;
    int k = i / N, n = i % N;
    Bt[(size_t)n * ldBt + kOff + k] = rtf(B[(size_t)k * N + n]);
}

struct TSeg { const float* B; float* Bt; int K; int N; int ldBt; int kOff; };
struct TSegs { TSeg s[10]; };

__global__ void k_transAll(TSegs P) {
    TSeg sg = P.s[blockIdx.y];
    int i = blockIdx.x * blockDim.x + threadIdx.x;
    if (i >= sg.K * sg.N) return;
    int k = i / sg.N, n = i % sg.N;
    sg.Bt[(size_t)n * sg.ldBt + sg.kOff + k] = rtf(sg.B[(size_t)k * sg.N + n]);
}

__global__ void k_round4(const float4* __restrict__ in, float4* __restrict__ out, int n4) {
    int i = blockIdx.x * blockDim.x + threadIdx.x;
    if (i >= n4) return;
    float4 v = in[i];
    v.x = rtf(v.x); v.y = rtf(v.y); v.z = rtf(v.z); v.w = rtf(v.w);
    out[i] = v;
}

// ---------------- SAGE mean-gather ----------------
template <int D>
__global__ __launch_bounds__(D) void k_sage_gather(const float* __restrict__ xin,
                                                   float* __restrict__ agg) {
    constexpr int L = D / 4;
    __shared__ float4 sred[4][L];
    int n = blockIdx.x;
    int tid = threadIdx.x;
    int grp = tid / L, lane = tid % L;
    int base = g_rowstart[n], deg = g_deg[n];
    const float4* xin4 = (const float4*)xin;
    float4 acc = make_float4(0.f, 0.f, 0.f, 0.f);
    for (int j = grp; j < deg; j += 4) {
        int s = g_es[base + j];
        float4 v = xin4[(size_t)s * L + lane];
        acc.x += v.x; acc.y += v.y; acc.z += v.z; acc.w += v.w;
    }
    sred[grp][lane] = acc;
    __syncthreads();
    if (grp == 0) {
        float4 a = sred[0][lane], b = sred[1][lane], c = sred[2][lane], d = sred[3][lane];
        float w = g_invdeg[n];
        float4 o;
        o.x = rtf((a.x + b.x + c.x + d.x) * w);
        o.y = rtf((a.y + b.y + c.y + d.y) * w);
        o.z = rtf((a.z + b.z + c.z + d.z) * w);
        o.w = rtf((a.w + b.w + c.w + d.w) * w);
        ((float4*)agg)[(size_t)n * L + lane] = o;
    }
}

// ---------------- TF32 GEMM: 64x128 tile, 3 CTAs/SM target, 4-stage cp.async ----------------
// warps: 2 (rows) x 4 (cols); warp tile 32x32
__global__ __launch_bounds__(256, 3) void tgemm(
    const float* __restrict__ A0, int K0,
    const float* __restrict__ A1, int K1,
    const float* __restrict__ A2, int K2,
    const float* __restrict__ Bt,
    float* __restrict__ C, const float* __restrict__ bias,
    int M, int Nc, int accFlag, int reluFlag, int roundFlag,
    size_t zsB, size_t zsC) {
    extern __shared__ float sm[];
    float* smA = sm;               // 4 stages * 64 rows * 20
    float* smB = sm + 4 * 1280;    // 4 stages * 128 rows * 20
#define ASX(st, r, c) smA[(st) * 1280 + (r) * 20 + (c)]
#define BSX(st, r, c) smB[(st) * 2560 + (r) * 20 + (c)]
    const int tid = threadIdx.x;
    const int m0 = blockIdx.y * 64, n0 = blockIdx.x * 128;
    const int wid = tid >> 5, lane = tid & 31;
    const int wm = wid & 1, wn = wid >> 1;     // 2 x 4 warps
    const int g = lane >> 2, tq = lane & 3;
    const int Ktot = K0 + K1 + K2;
    Bt += blockIdx.z * zsB;
    C  += blockIdx.z * zsC;
    const float* segA[3] = {A0, A1, A2};
    const int segK01 = K0 + K1;
    const int T = Ktot >> 4;

    float acc[2][4][4];
#pragma unroll
    for (int mt = 0; mt < 2; mt++)
#pragma unroll
        for (int nt = 0; nt < 4; nt++)
#pragma unroll
            for (int r = 0; r < 4; r++) acc[mt][nt][r] = 0.f;

    // A fill: row tid>>2 (64 rows), 4 cols at (tid&3)*4 -> one CP16
    const int aRow = tid >> 2;
    const int aColA = (tid & 3) * 4;
    const bool aValid = (m0 + aRow) < M;
    const int aR = aValid ? (m0 + aRow) : 0;
    // B fill: n row tid>>1 (128 rows), 8 cols at (tid&1)*8 -> two CP16
    const int bRowN = tid >> 1;
    const int bColK = (tid & 1) * 8;
    const float* BtRow = Bt + (size_t)(n0 + bRowN) * Ktot + bColK;

    const int aLr = (lane & 7) + (((lane >> 3) & 1) << 3);
    const int aLc = ((lane >> 4) & 1) * 4;
    const int bLr = (lane & 7) + (((lane >> 4) & 1) << 3);
    const int bLc = ((lane >> 3) & 1) * 4;

    auto issue = [&](int tile, int buf) {
        int kpos = tile * 16;
        int s, kk;
        if (kpos < K0) { s = 0; kk = kpos; }
        else if (kpos < segK01) { s = 1; kk = kpos - K0; }
        else { s = 2; kk = kpos - segK01; }
        int Ks = (s == 0) ? K0 : (s == 1) ? K1 : K2;
        const float* Ag = segA[s] + (size_t)aR * Ks + kk + aColA;
        unsigned sa = (unsigned)__cvta_generic_to_shared(&ASX(buf, aRow, aColA));
        CP16(sa, Ag);
        const float* Bg = BtRow + kpos;
        unsigned sb = (unsigned)__cvta_generic_to_shared(&BSX(buf, bRowN, bColK));
        CP16(sb, Bg); CP16(sb + 16, Bg + 4);
    };

    for (int p = 0; p < 3 && p < T; p++) { issue(p, p); CPCOMMIT(); }

    for (int t = 0; t < T; t++) {
        CPWAIT(2);
        __syncthreads();
        if (t + 3 < T) issue(t + 3, (t + 3) & 3);
        CPCOMMIT();
        const int pb = t & 3;
#pragma unroll
        for (int ks = 0; ks < 16; ks += 8) {
            unsigned af[2][4], bf[2][4];
#pragma unroll
            for (int mt = 0; mt < 2; mt++) {
                unsigned addr = (unsigned)__cvta_generic_to_shared(
                    &ASX(pb, wm * 32 + mt * 16 + aLr, ks + aLc));
                asm volatile("ldmatrix.sync.aligned.m8n8.x4.shared.b16 {%0,%1,%2,%3}, [%4];"
                    : "=r"(af[mt][0]), "=r"(af[mt][1]), "=r"(af[mt][2]), "=r"(af[mt][3])
                    : "r"(addr));
            }
#pragma unroll
            for (int np = 0; np < 2; np++) {
                unsigned addr = (unsigned)__cvta_generic_to_shared(
                    &BSX(pb, wn * 32 + np * 16 + bLr, ks + bLc));
                asm volatile("ldmatrix.sync.aligned.m8n8.x4.shared.b16 {%0,%1,%2,%3}, [%4];"
                    : "=r"(bf[np][0]), "=r"(bf[np][1]), "=r"(bf[np][2]), "=r"(bf[np][3])
                    : "r"(addr));
            }
#pragma unroll
            for (int mt = 0; mt < 2; mt++)
#pragma unroll
                for (int nt = 0; nt < 4; nt++) {
                    unsigned b0 = bf[nt >> 1][(nt & 1) * 2 + 0];
                    unsigned b1 = bf[nt >> 1][(nt & 1) * 2 + 1];
                    float* c = acc[mt][nt];
                    asm volatile(
                        "mma.sync.aligned.m16n8k8.row.col.f32.tf32.tf32.f32 "
                        "{%0,%1,%2,%3}, {%4,%5,%6,%7}, {%8,%9}, {%0,%1,%2,%3};"
                        : "+f"(c[0]), "+f"(c[1]), "+f"(c[2]), "+f"(c[3])
                        : "r"(af[mt][0]), "r"(af[mt][1]), "r"(af[mt][2]), "r"(af[mt][3]),
                          "r"(b0), "r"(b1));
                }
        }
    }

#pragma unroll
    for (int mt = 0; mt < 2; mt++) {
        int r0 = m0 + wm * 32 + mt * 16 + g;
#pragma unroll
        for (int half = 0; half < 2; half++) {
            int row = r0 + half * 8;
            if (row >= M) continue;
#pragma unroll
            for (int nt = 0; nt < 4; nt++) {
                int col = n0 + wn * 32 + nt * 8 + 2 * tq;
                float* p = C + (size_t)row * Nc + col;
                float2 cv;
                cv.x = acc[mt][nt][half * 2 + 0];
                cv.y = acc[mt][nt][half * 2 + 1];
                if (accFlag) { float2 o = *(const float2*)p; cv.x += o.x; cv.y += o.y; }
                if (bias != nullptr) { cv.x += bias[col]; cv.y += bias[col + 1]; }
                if (reluFlag) { cv.x = fmaxf(cv.x, 0.f); cv.y = fmaxf(cv.y, 0.f); }
                if (roundFlag) { cv.x = rtf(cv.x); cv.y = rtf(cv.y); }
                *(float2*)p = cv;
            }
        }
    }
#undef ASX
#undef BSX
}

// ---------------- GAT: per-node attention logits (float4) ----------------
__global__ __launch_bounds__(256) void k_al(const float* __restrict__ aS,
                                            const float* __restrict__ aD) {
    int gw = (int)(((size_t)blockIdx.x * blockDim.x + threadIdx.x) >> 5);
    int lane = threadIdx.x & 31;
    if (gw >= NN * 2) return;
    int n = gw >> 1, k = gw & 1;
    const float4* hp = (const float4*)(g_h + (size_t)n * 512 + k * 256);
    const float4* as4 = (const float4*)(aS + k * 256);
    const float4* ad4 = (const float4*)(aD + k * 256);
    float ss = 0.f, sd = 0.f;
#pragma unroll
    for (int it = 0; it < 2; it++) {
        int j = lane + it * 32;
        float4 h = hp[j], A = as4[j], D = ad4[j];
        ss += h.x * A.x + h.y * A.y + h.z * A.z + h.w * A.w;
        sd += h.x * D.x + h.y * D.y + h.z * D.z + h.w * D.w;
    }
#pragma unroll
    for (int o = 16; o; o >>= 1) {
        ss += __shfl_down_sync(0xffffffffu, ss, o);
        sd += __shfl_down_sync(0xffffffffu, sd, o);
    }
    if (lane == 0) { g_als[gw] = ss; g_ald[gw] = sd; }
}

// ---------------- GAT: online-softmax, thread owns float2 of features ----------------
__global__ __launch_bounds__(256) void k_gat(const float* __restrict__ bias) {
    __shared__ float sW0[256], sW1[256];
    __shared__ int   sS[256];
    __shared__ float wm0[8], wm1[8];
    __shared__ float2 stage[128];
    int n = blockIdx.x;
    int t = threadIdx.x;
    int lane = t & 31, warp = t >> 5;
    int base = g_rowstart[n], deg = g_deg[n];

    float ald0 = g_ald[2 * n], ald1 = g_ald[2 * n + 1];
    float m0 = lrelu(g_als[2 * n] + ald0);
    float m1 = lrelu(g_als[2 * n + 1] + ald1);
    float d0 = 1.f, d1 = 1.f;
    const float2* h2 = (const float2*)g_h;
    float2 a = h2[(size_t)n * 256 + t];
    bool head0 = (t < 128);

    for (int c0 = 0; c0 < deg; c0 += 256) {
        int cnt = min(256, deg - c0);
        float e0 = -1e30f, e1 = -1e30f;
        int sNode = 0;
        if (t < cnt) {
            sNode = g_es[base + c0 + t];
            e0 = lrelu(g_als[2 * sNode] + ald0);
            e1 = lrelu(g_als[2 * sNode + 1] + ald1);
        }
        float w0r = e0, w1r = e1;
#pragma unroll
        for (int o = 16; o; o >>= 1) {
            w0r = fmaxf(w0r, __shfl_xor_sync(0xffffffffu, w0r, o));
            w1r = fmaxf(w1r, __shfl_xor_sync(0xffffffffu, w1r, o));
        }
        if (lane == 0) { wm0[warp] = w0r; wm1[warp] = w1r; }
        __syncthreads();
        float cm0 = wm0[0], cm1 = wm1[0];
#pragma unroll
        for (int w = 1; w < 8; w++) { cm0 = fmaxf(cm0, wm0[w]); cm1 = fmaxf(cm1, wm1[w]); }

        float M0 = fmaxf(m0, cm0), M1 = fmaxf(m1, cm1);
        float sc0 = expf(m0 - M0), sc1 = expf(m1 - M1);
        float scMe = head0 ? sc0 : sc1;
        a.x *= scMe; a.y *= scMe;
        d0 *= sc0; d1 *= sc1; m0 = M0; m1 = M1;

        if (t < cnt) {
            sS[t] = sNode;
            sW0[t] = expf(e0 - m0);
            sW1[t] = expf(e1 - m1);
        }
        __syncthreads();
        for (int j = 0; j < cnt; j++) {
            float w0 = sW0[j], w1 = sW1[j];
            float w = head0 ? w0 : w1;
            float2 hv = h2[(size_t)sS[j] * 256 + t];
            a.x += w * hv.x; a.y += w * hv.y;
            d0 += w0; d1 += w1;
        }
        __syncthreads();
    }
    float i0 = 1.f / fmaxf(d0, 1e-16f), i1 = 1.f / fmaxf(d1, 1e-16f);
    if (!head0) stage[t - 128] = a;
    __syncthreads();
    if (head0) {
        float2 b1 = stage[t];
        float v0 = 0.5f * (a.x * i0 + b1.x * i1) + bias[2 * t];
        float v1 = 0.5f * (a.y * i0 + b1.y * i1) + bias[2 * t + 1];
        float2 o;
        o.x = rtf(fmaxf(v0, 0.f));
        o.y = rtf(fmaxf(v1, 0.f));
        ((float2*)g_xgat)[(size_t)n * 128 + t] = o;
    }
}

// ---------------- RGCN gather ----------------
__global__ __launch_bounds__(128) void k_rgcn() {
    __shared__ float4 sred[4][32];
    int n = blockIdx.x;
    int t = threadIdx.x;
    int grp = t >> 5, lane = t & 31;
    int base = g_rowstart[n], deg = g_deg[n];
    float w0 = g_invcnt4[n * 4 + 0], w1 = g_invcnt4[n * 4 + 1];
    float w2 = g_invcnt4[n * 4 + 2], w3 = g_invcnt4[n * 4 + 3];
    const float4* xt4 = (const float4*)g_xt;
    float4 acc = make_float4(0.f, 0.f, 0.f, 0.f);
    for (int j = grp; j < deg; j += 4) {
        int s = g_es[base + j];
        int r = g_etl[base + j];
        float w = (r == 0) ? w0 : (r == 1) ? w1 : (r == 2) ? w2 : w3;
        float4 v = xt4[((size_t)r * NN + s) * 32 + lane];
        acc.x += w * v.x; acc.y += w * v.y; acc.z += w * v.z; acc.w += w * v.w;
    }
    sred[grp][lane] = acc;
    __syncthreads();
    if (grp == 0) {
        float4 A = sred[0][lane], B = sred[1][lane], C = sred[2][lane], D = sred[3][lane];
        float4 o;
        o.x = rtf(A.x + B.x + C.x + D.x);
        o.y = rtf(A.y + B.y + C.y + D.y);
        o.z = rtf(A.z + B.z + C.z + D.z);
        o.w = rtf(A.w + B.w + C.w + D.w);
        ((float4*)g_xrgcn)[(size_t)n * 32 + lane] = o;
    }
}

// ---------------- fold rgcn root into fusion weights ----------------
__global__ void k_compose(const float* __restrict__ fW, const float* __restrict__ fB,
                          const float* __restrict__ Wroot, const float* __restrict__ rgcB,
                          float* __restrict__ btfus) {
    int b = blockIdx.x, t = threadIdx.x;
    const float* F3 = fW + 512 * EMBD;
    if (b < HID) {
        float acc = fW[(256 + b) * EMBD + t];
        for (int h = 0; h < EMBD; h++)
            acc += Wroot[b * EMBD + h] * F3[h * EMBD + t];
        btfus[(size_t)t * 640 + 256 + b] = rtf(acc);
    } else {
        float acc = fB[t];
        for (int h = 0; h < EMBD; h++)
            acc += rgcB[h] * F3[h * EMBD + t];
        g_fb2[t] = acc;
    }
}

// ---------------- final L2 normalize ----------------
__global__ void k_norm(float* __restrict__ out) {
    int n = blockIdx.x;
    int t = threadIdx.x;
    float v = out[(size_t)n * EMBD + t];
    float s = v * v;
#pragma unroll
    for (int o = 16; o; o >>= 1) s += __shfl_down_sync(0xffffffffu, s, o);
    __shared__ float sh[4];
    if ((t & 31) == 0) sh[t >> 5] = s;
    __syncthreads();
    float tot = sh[0] + sh[1] + sh[2] + sh[3];
    float nrm = fmaxf(sqrtf(tot), 1e-12f);
    out[(size_t)n * EMBD + t] = v / nrm;
}

// ---------------- host ----------------
#define TG_SMEM (4 * (1280 + 2560) * 4)

static void launch_seg(const float* A0, int K0, const float* A1, int K1,
                       const float* A2, int K2, const float* Bt,
                       float* C, const float* bias, int M, int Nc,
                       int acc, int relu, int rnd,
                       int gz = 1, size_t zsB = 0, size_t zsC = 0) {
    dim3 grid(Nc / 128, (M + 63) / 64, gz);
    tgemm<<<grid, 256, TG_SMEM>>>(A0, K0, A1, K1, A2, K2, Bt, C, bias, M, Nc,
                                  acc, relu, rnd, zsB, zsC);
}

extern "C" void kernel_launch(void* const* d_in, const int* in_sizes, int n_in,
                              void* d_out, int out_size) {
    const float* x    = (const float*)d_in[0];
    const int*   ei   = (const int*)d_in[1];
    const int*   et   = (const int*)d_in[2];
    const float* s1Wl = (const float*)d_in[3];
    const float* s1Wr = (const float*)d_in[4];
    const float* s1b  = (const float*)d_in[5];
    const float* s2Wl = (const float*)d_in[6];
    const float* s2Wr = (const float*)d_in[7];
    const float* s2b  = (const float*)d_in[8];
    const float* gatW = (const float*)d_in[9];
    const float* aSrc = (const float*)d_in[10];
    const float* aDst = (const float*)d_in[11];
    const float* gatB = (const float*)d_in[12];
    const float* Wrel = (const float*)d_in[13];
    const float* Wroot= (const float*)d_in[14];
    const float* rgcB = (const float*)d_in[15];
    const float* fW   = (const float*)d_in[16];
    const float* fB   = (const float*)d_in[17];
    float* out = (float*)d_out;

    const int* src = ei;
    const int* dst = ei + EE;

    cudaFuncSetAttribute(tgemm, cudaFuncAttributeMaxDynamicSharedMemorySize, TG_SMEM);

    float *p_xr, *p_agg1, *p_x1, *p_agg2, *p_xsage, *p_h, *p_xgat, *p_xt, *p_xrgcn, *p_fb2;
    float *p_bt1r, *p_bt1l, *p_bt2, *p_btg, *p_btrel, *p_btfus;
    cudaGetSymbolAddress((void**)&p_xr, g_xr);
    cudaGetSymbolAddress((void**)&p_agg1, g_agg1);
    cudaGetSymbolAddress((void**)&p_x1, g_x1);
    cudaGetSymbolAddress((void**)&p_agg2, g_agg2);
    cudaGetSymbolAddress((void**)&p_xsage, g_xsage);
    cudaGetSymbolAddress((void**)&p_h, g_h);
    cudaGetSymbolAddress((void**)&p_xgat, g_xgat);
    cudaGetSymbolAddress((void**)&p_xt, g_xt);
    cudaGetSymbolAddress((void**)&p_xrgcn, g_xrgcn);
    cudaGetSymbolAddress((void**)&p_fb2, g_fb2);
    cudaGetSymbolAddress((void**)&p_bt1r, g_bt1r);
    cudaGetSymbolAddress((void**)&p_bt1l, g_bt1l);
    cudaGetSymbolAddress((void**)&p_bt2, g_bt2);
    cudaGetSymbolAddress((void**)&p_btg, g_btg);
    cudaGetSymbolAddress((void**)&p_btrel, g_btrel);
    cudaGetSymbolAddress((void**)&p_btfus, g_btfus);

    // launches 1-4 (ncu profiles #4 -> a GEMM)
    k_zero_small<<<(NN * RR + 255) / 256, 256>>>();                             // 1
    k_transB<<<(128 * 256 + 255) / 256, 256>>>(s1Wr, p_bt1r, 128, 256, 128, 0); // 2
    k_round4<<<(NN * IN_C / 4 + 255) / 256, 256>>>((const float4*)x, (float4*)p_xr,
                                                   NN * IN_C / 4);              // 3
    launch_seg(p_xr, IN_C, 0, 0, 0, 0, p_bt1r, p_x1, nullptr,
               NN, HID, 0, 0, 0);                                               // 4

    // CSR build
    k_count<<<(EE + 255) / 256, 256>>>(dst, et);
    k_scan1<<<NBLK, 256>>>();
    k_scan2<<<1, 256>>>();
    k_scan3_inv<<<NBLK, 256>>>();
    k_fill<<<(EE + 255) / 256, 256>>>(src, dst, et);

    // remaining weight transposes in one launch
    TSegs ts;
    ts.s[0] = {s1Wl, p_bt1l, 128, 256, 128, 0};
    ts.s[1] = {s2Wl, p_bt2, 256, 256, 512, 0};
    ts.s[2] = {s2Wr, p_bt2, 256, 256, 512, 256};
    ts.s[3] = {gatW, p_btg, 256, 512, 256, 0};
    ts.s[4] = {Wrel + 0 * (size_t)HID * EMBD, p_btrel + 0 * (size_t)128 * 256, 256, 128, 256, 0};
    ts.s[5] = {Wrel + 1 * (size_t)HID * EMBD, p_btrel + 1 * (size_t)128 * 256, 256, 128, 256, 0};
    ts.s[6] = {Wrel + 2 * (size_t)HID * EMBD, p_btrel + 2 * (size_t)128 * 256, 256, 128, 256, 0};
    ts.s[7] = {Wrel + 3 * (size_t)HID * EMBD, p_btrel + 3 * (size_t)128 * 256, 256, 128, 256, 0};
    ts.s[8] = {fW, p_btfus, 256, 128, 640, 0};
    ts.s[9] = {fW + 512 * EMBD, p_btfus, 128, 128, 640, 512};
    k_transAll<<<dim3(512, 10), 256>>>(ts);
    k_compose<<<HID + 1, EMBD>>>(fW, fB, Wroot, rgcB, p_btfus);

    // ---- SAGE 1 ----
    k_sage_gather<IN_C><<<NN, IN_C>>>(x, p_agg1);
    launch_seg(p_agg1, IN_C, 0, 0, 0, 0, p_bt1l, p_x1, s1b, NN, HID, 1, 1, 1);

    // ---- SAGE 2 ----
    k_sage_gather<HID><<<NN, HID>>>(p_x1, p_agg2);
    launch_seg(p_agg2, HID, p_x1, HID, 0, 0, p_bt2, p_xsage, s2b, NN, HID, 0, 1, 1);

    // ---- GAT ----
    launch_seg(p_xsage, HID, 0, 0, 0, 0, p_btg, p_h, nullptr, NN, 2 * HID, 0, 0, 0);
    k_al<<<(NN * 2 * 32 + 255) / 256, 256>>>(aSrc, aDst);
    k_gat<<<NN, 256>>>(gatB);

    // ---- RGCN ----
    launch_seg(p_xgat, HID, 0, 0, 0, 0, p_btrel, p_xt, nullptr, NN, EMBD, 0, 0, 0,
               RR, (size_t)128 * 256, (size_t)NN * EMBD);
    k_rgcn<<<NN, 128>>>();

    // ---- Fusion + normalize ----
    launch_seg(p_xsage, HID, p_xgat, HID, p_xrgcn, EMBD, p_btfus,
               out, p_fb2, NN, EMBD, 0, 0, 0);
    k_norm<<<NN, 128>>>(out);
}